// round 1
// baseline (speedup 1.0000x reference)
#include <cuda_runtime.h>
#include <cstdint>

// ---------------------------------------------------------------------------
// SynapticPlasticityModule on GB300.
// Outputs (in d_out, fp32, in tuple order):
//   [0 .. B*H)                       output = x @ (W * meta)
//   [B*H .. B*H+H*H)                 new_w
//   [.. +H)                          new_meta
//   [.. +ACT)                        hist
// ---------------------------------------------------------------------------

#define H_DIM 1024
#define HIST_LEN 100
#define SPLIT 64           // row-groups for column-sum reduction

// __device__ scratch (allocation-free rule)
__device__ float g_part[SPLIT * H_DIM];
__device__ float g_xmean[H_DIM];
__device__ float g_omean[H_DIM];
__device__ float g_a[H_DIM];
__device__ float g_b[H_DIM];
__device__ float g_scal[2];   // [0] = overall output mean, [1] = homeostatic factor

// ---------------------------------------------------------------------------
// GEMM: C[MxN] = A[MxK] @ (W[KxN] * meta[N])   (column scaling fused)
// 128x128x16 block tile, 8x8 per thread, 256 threads.
// ---------------------------------------------------------------------------
__global__ __launch_bounds__(256) void gemm128(
    const float* __restrict__ A, const float* __restrict__ W,
    const float* __restrict__ meta, float* __restrict__ C,
    int M, int K, int N)
{
    __shared__ float As[16][128];
    __shared__ float Bs[16][128];
    __shared__ float ms[128];

    const int tid = threadIdx.x;
    const int bx = blockIdx.x;   // N tile
    const int by = blockIdx.y;   // M tile

    if (tid < 32)
        reinterpret_cast<float4*>(ms)[tid] =
            reinterpret_cast<const float4*>(meta + bx * 128)[tid];
    __syncthreads();

    const int trow = tid / 16;   // 0..15
    const int tcol = tid % 16;   // 0..15

    float acc[8][8];
#pragma unroll
    for (int i = 0; i < 8; i++)
#pragma unroll
        for (int j = 0; j < 8; j++) acc[i][j] = 0.0f;

    const float* Ab = A + (size_t)by * 128 * K;
    const float* Wb = W + (size_t)bx * 128;

    for (int k0 = 0; k0 < K; k0 += 16) {
        // load A tile 128x16, store transposed As[k][m]
#pragma unroll
        for (int l = 0; l < 2; l++) {
            int p  = tid + l * 256;        // 0..511
            int ar = p >> 2;               // 0..127  (row in tile)
            int kq = p & 3;                // float4 group within BK
            float4 v = *reinterpret_cast<const float4*>(Ab + (size_t)ar * K + k0 + kq * 4);
            As[kq * 4 + 0][ar] = v.x;
            As[kq * 4 + 1][ar] = v.y;
            As[kq * 4 + 2][ar] = v.z;
            As[kq * 4 + 3][ar] = v.w;
        }
        // load B tile 16x128 with fused meta scaling
#pragma unroll
        for (int l = 0; l < 2; l++) {
            int p  = tid + l * 256;
            int br = p >> 5;               // 0..15 (k row)
            int bc = p & 31;               // float4 column
            float4 v  = *reinterpret_cast<const float4*>(Wb + (size_t)(k0 + br) * N + bc * 4);
            float4 mv = reinterpret_cast<float4*>(ms)[bc];
            Bs[br][bc * 4 + 0] = v.x * mv.x;
            Bs[br][bc * 4 + 1] = v.y * mv.y;
            Bs[br][bc * 4 + 2] = v.z * mv.z;
            Bs[br][bc * 4 + 3] = v.w * mv.w;
        }
        __syncthreads();

#pragma unroll
        for (int kk = 0; kk < 16; kk++) {
            float4 a0 = *reinterpret_cast<const float4*>(&As[kk][trow * 8]);
            float4 a1 = *reinterpret_cast<const float4*>(&As[kk][trow * 8 + 4]);
            float4 b0 = *reinterpret_cast<const float4*>(&Bs[kk][tcol * 8]);
            float4 b1 = *reinterpret_cast<const float4*>(&Bs[kk][tcol * 8 + 4]);
            float ra[8] = {a0.x, a0.y, a0.z, a0.w, a1.x, a1.y, a1.z, a1.w};
            float rb[8] = {b0.x, b0.y, b0.z, b0.w, b1.x, b1.y, b1.z, b1.w};
#pragma unroll
            for (int i = 0; i < 8; i++)
#pragma unroll
                for (int j = 0; j < 8; j++)
                    acc[i][j] = fmaf(ra[i], rb[j], acc[i][j]);
        }
        __syncthreads();
    }

#pragma unroll
    for (int i = 0; i < 8; i++) {
        size_t row = (size_t)(by * 128 + trow * 8 + i);
        float4* cp = reinterpret_cast<float4*>(C + row * N + bx * 128 + tcol * 8);
        cp[0] = make_float4(acc[i][0], acc[i][1], acc[i][2], acc[i][3]);
        cp[1] = make_float4(acc[i][4], acc[i][5], acc[i][6], acc[i][7]);
    }
}

// ---------------------------------------------------------------------------
// Column-sum stage 1: each block sums rows_per rows for 256 columns.
// grid = (H/256, SPLIT)
// ---------------------------------------------------------------------------
__global__ __launch_bounds__(256) void colsum_part(const float* __restrict__ src, int rows_per)
{
    int h = blockIdx.x * 256 + threadIdx.x;
    const float* p = src + (size_t)blockIdx.y * rows_per * H_DIM + h;
    float s = 0.0f;
    for (int r = 0; r < rows_per; r++) s += p[(size_t)r * H_DIM];
    g_part[blockIdx.y * H_DIM + h] = s;
}

// Column-sum stage 2: reduce SPLIT partials, scale by 1/B, store to mean buf.
__global__ __launch_bounds__(256) void colsum_reduce(int toX, float invB)
{
    int h = blockIdx.x * 256 + threadIdx.x;
    float s = 0.0f;
#pragma unroll
    for (int i = 0; i < SPLIT; i++) s += g_part[i * H_DIM + h];
    if (toX) g_xmean[h] = s * invB;
    else     g_omean[h] = s * invB;
}

// ---------------------------------------------------------------------------
// STDP weighted history sums:
//   g_a[h] = sum_{i=0..98} w[i] * pre_hist[i+1][h]
//   g_b[h] = sum_{i=1..98} w[i] * post_hist[i+1][h] + w[99]*omean[h]
//   with w[i] = 0.01 * exp(-(100-i)*window*decay)
// ---------------------------------------------------------------------------
__global__ __launch_bounds__(256) void stdp_vec(
    const float* __restrict__ pre_hist, const float* __restrict__ post_hist,
    const float* __restrict__ d_win, const float* __restrict__ d_dec)
{
    int h = blockIdx.x * 256 + threadIdx.x;
    float win = *d_win, dec = *d_dec;
    float a = 0.0f, b = 0.0f;
    for (int i = 0; i < 99; i++) {
        float dt = (float)(HIST_LEN - i) * win;
        float wv = 0.01f * expf(-dt * dec);
        a += wv * pre_hist[(i + 1) * H_DIM + h];
        if (i >= 1) b += wv * post_hist[(i + 1) * H_DIM + h];
    }
    float w99 = 0.01f * expf(-(1.0f * win) * dec);
    b += w99 * g_omean[h];
    g_a[h] = a;
    g_b[h] = b;
}

// ---------------------------------------------------------------------------
// Scalars + hist output. Single block.
// ---------------------------------------------------------------------------
__global__ __launch_bounds__(256) void scalars_kernel(
    const float* __restrict__ act, const int* __restrict__ d_ptr,
    const float* __restrict__ d_target, const float* __restrict__ d_hrate,
    float* __restrict__ out_hist, int act_len)
{
    __shared__ float red[256];
    int tid = threadIdx.x;

    // overall output mean = mean over H of column means
    float s = 0.0f;
    for (int h = tid; h < H_DIM; h += 256) s += g_omean[h];
    red[tid] = s;
    __syncthreads();
    for (int o = 128; o > 0; o >>= 1) {
        if (tid < o) red[tid] += red[tid + o];
        __syncthreads();
    }
    float m = red[0] / (float)H_DIM;
    __syncthreads();

    // activity history sum
    float as = 0.0f;
    for (int i = tid; i < act_len; i += 256) as += act[i];
    red[tid] = as;
    __syncthreads();
    for (int o = 128; o > 0; o >>= 1) {
        if (tid < o) red[tid] += red[tid + o];
        __syncthreads();
    }
    int ptr = *d_ptr;
    float hist_mean = (red[0] - act[ptr] + m) / (float)act_len;
    float factor = 1.0f + (*d_hrate) * ((*d_target) - hist_mean);

    if (tid == 0) { g_scal[0] = m; g_scal[1] = factor; }

    // write hist output
    for (int i = tid; i < act_len; i += 256)
        out_hist[i] = (i == ptr) ? m : act[i];
}

// ---------------------------------------------------------------------------
// Weight update: new_w = clip(clip(W + dW, -1, 1) * factor, -1, 1)
//   dW[r][c] = omean[r]*g_a[c] - g_b[r]*xmean[c]
// ---------------------------------------------------------------------------
__global__ __launch_bounds__(256) void weights_kernel(
    const float* __restrict__ W, float* __restrict__ out_w)
{
    size_t idx = (size_t)blockIdx.x * 256 + threadIdx.x;
    int r = (int)(idx >> 10);
    int c = (int)(idx & (H_DIM - 1));
    float factor = g_scal[1];
    float v = W[idx] + g_omean[r] * g_a[c] - g_b[r] * g_xmean[c];
    v = fminf(fmaxf(v, -1.0f), 1.0f);
    v *= factor;
    v = fminf(fmaxf(v, -1.0f), 1.0f);
    out_w[idx] = v;
}

// ---------------------------------------------------------------------------
// Meta plasticity update
// ---------------------------------------------------------------------------
__global__ __launch_bounds__(256) void meta_kernel(
    const float* __restrict__ meta, const float* __restrict__ d_mlr,
    float* __restrict__ out_meta)
{
    int h = blockIdx.x * 256 + threadIdx.x;
    float mlr = *d_mlr;
    float v = meta[h] + mlr * (g_omean[h] - meta[h]);
    v = fminf(fmaxf(v, 0.0f), 2.0f);
    out_meta[h] = v;
}

// ---------------------------------------------------------------------------
extern "C" void kernel_launch(void* const* d_in, const int* in_sizes, int n_in,
                              void* d_out, int out_size)
{
    const float* x      = (const float*)d_in[0];
    const float* W      = (const float*)d_in[1];
    const float* meta   = (const float*)d_in[2];
    const float* pre    = (const float*)d_in[3];
    const float* post   = (const float*)d_in[4];
    const float* act    = (const float*)d_in[5];
    const int*   ptr    = (const int*)d_in[6];
    const float* win    = (const float*)d_in[7];
    const float* dec    = (const float*)d_in[8];
    const float* target = (const float*)d_in[9];
    const float* hrate  = (const float*)d_in[10];
    const float* mlr    = (const float*)d_in[11];

    const int H = H_DIM;
    const int B = in_sizes[0] / H;          // 16384
    const int ACT = in_sizes[5];            // 1000

    float* out      = (float*)d_out;
    float* out_w    = out + (size_t)B * H;
    float* out_meta = out_w + (size_t)H * H;
    float* out_hist = out_meta + H;

    // 1) GEMM (writes output region)
    dim3 ggrid(H / 128, B / 128);
    gemm128<<<ggrid, 256>>>(x, W, meta, out, B, H, H);

    const float invB = 1.0f / (float)B;
    const int rows_per = B / SPLIT;

    // 2) x column means
    dim3 cgrid(H / 256, SPLIT);
    colsum_part<<<cgrid, 256>>>(x, rows_per);
    colsum_reduce<<<H / 256, 256>>>(1, invB);

    // 3) output column means
    colsum_part<<<cgrid, 256>>>(out, rows_per);
    colsum_reduce<<<H / 256, 256>>>(0, invB);

    // 4) STDP history dot products
    stdp_vec<<<H / 256, 256>>>(pre, post, win, dec);

    // 5) scalars + hist output
    scalars_kernel<<<1, 256>>>(act, ptr, target, hrate, out_hist, ACT);

    // 6) weight update
    weights_kernel<<<(H * H) / 256, 256>>>(W, out_w);

    // 7) meta update
    meta_kernel<<<H / 256, 256>>>(meta, mlr, out_meta);
}

// round 3
// speedup vs baseline: 5.1452x; 5.1452x over previous
#include <cuda_runtime.h>
#include <cuda_fp16.h>
#include <cstdint>

// ---------------------------------------------------------------------------
// SynapticPlasticityModule on GB300 — mma.sync fp16 GEMM (sm_103-safe) + chain.
// Outputs (d_out, fp32): [output B*H][new_w H*H][new_meta H][hist ACT]
// ---------------------------------------------------------------------------

#define H_DIM 1024
#define B_DIM 16384
#define HIST_LEN 100
#define SPLIT 128

#define TM 128
#define TN 128
#define KC 64
#define NCHUNK (H_DIM / KC)                 // 16
#define STAGE_BYTES (TM * 128 + TN * 128)   // 32768 (A tile + B tile, 128B rows)
#define GEMM_SMEM (2 * STAGE_BYTES)         // 65536

// __device__ scratch (allocation-free rule: static module storage)
__device__ __half g_xh[(size_t)B_DIM * H_DIM];   // x fp16          (32 MB)
__device__ __half g_wh[(size_t)H_DIM * H_DIM];   // (W*meta)^T fp16 ( 2 MB)
__device__ float  g_part[SPLIT * H_DIM];
__device__ float  g_xmean[H_DIM];
__device__ float  g_omean[H_DIM];
__device__ float  g_a[H_DIM];
__device__ float  g_b[H_DIM];
__device__ float  g_scal[2];

__device__ __forceinline__ uint32_t smem_u32(const void* p) {
    uint32_t a;
    asm("{ .reg .u64 t; cvta.to.shared.u64 t, %1; cvt.u32.u64 %0, t; }"
        : "=r"(a) : "l"(p));
    return a;
}
#define SW128(off) ((off) ^ (((off) >> 3) & 0x70))

#define CP_ASYNC16(smem_addr, gptr) \
    asm volatile("cp.async.cg.shared.global [%0], [%1], 16;" \
                 :: "r"(smem_addr), "l"(gptr) : "memory")
#define CP_COMMIT() asm volatile("cp.async.commit_group;" ::: "memory")
#define CP_WAIT1()  asm volatile("cp.async.wait_group 1;" ::: "memory")
#define CP_WAIT0()  asm volatile("cp.async.wait_group 0;" ::: "memory")

__device__ __forceinline__ void ldmx4(uint32_t* r, uint32_t addr) {
    asm volatile("ldmatrix.sync.aligned.m8n8.x4.shared.b16 {%0,%1,%2,%3}, [%4];"
                 : "=r"(r[0]), "=r"(r[1]), "=r"(r[2]), "=r"(r[3]) : "r"(addr));
}
__device__ __forceinline__ void mma16816(float* d, const uint32_t* a,
                                         const uint32_t* b) {
    asm volatile(
        "mma.sync.aligned.m16n8k16.row.col.f32.f16.f16.f32 "
        "{%0,%1,%2,%3}, {%4,%5,%6,%7}, {%8,%9}, {%0,%1,%2,%3};"
        : "+f"(d[0]), "+f"(d[1]), "+f"(d[2]), "+f"(d[3])
        : "r"(a[0]), "r"(a[1]), "r"(a[2]), "r"(a[3]), "r"(b[0]), "r"(b[1]));
}

// ---------------------------------------------------------------------------
// convert_x: fp32 -> fp16, fused column partial sums.  grid (H/256, SPLIT)
// ---------------------------------------------------------------------------
__global__ __launch_bounds__(256) void convert_x(const float* __restrict__ x, int rows_per)
{
    int h = blockIdx.x * 256 + threadIdx.x;
    size_t base = (size_t)blockIdx.y * rows_per * H_DIM + h;
    float s = 0.0f;
    for (int r = 0; r < rows_per; r++) {
        float v = x[base + (size_t)r * H_DIM];
        s += v;
        g_xh[base + (size_t)r * H_DIM] = __float2half_rn(v);
    }
    g_part[blockIdx.y * H_DIM + h] = s;
}

// convert_w: (W[k][n]*meta[n]) -> g_wh[n][k] fp16 (transposed). grid(32,32) blk(32,8)
__global__ void convert_w(const float* __restrict__ W, const float* __restrict__ meta)
{
    __shared__ float tile[32][33];
    int n0 = blockIdx.x * 32, k0 = blockIdx.y * 32;
    int tx = threadIdx.x, ty = threadIdx.y;
#pragma unroll
    for (int i = ty; i < 32; i += 8)
        tile[i][tx] = W[(size_t)(k0 + i) * H_DIM + n0 + tx] * meta[n0 + tx];
    __syncthreads();
#pragma unroll
    for (int i = ty; i < 32; i += 8)
        g_wh[(size_t)(n0 + i) * H_DIM + k0 + tx] = __float2half_rn(tile[tx][i]);
}

// ---------------------------------------------------------------------------
// GEMM: C[M,N] = A[M,K] @ B[N,K]^T  (fp16 in, fp32 out), mma.sync path.
// 128x128x64 tiles, 8 warps (4x2 of 32x64), cp.async double buffer.
// ---------------------------------------------------------------------------
__global__ __launch_bounds__(256) void gemm_mma(float* __restrict__ C)
{
    extern __shared__ char smem[];
    const uint32_t sb = smem_u32(smem);
    const int tid  = threadIdx.x;
    const int wid  = tid >> 5;
    const int lane = tid & 31;
    const int m0 = blockIdx.y * TM;
    const int n0 = blockIdx.x * TN;
    const int m_w = (wid & 3) * 32;
    const int n_w = (wid >> 2) * 64;

    float acc[2][8][4];
#pragma unroll
    for (int i = 0; i < 2; i++)
#pragma unroll
        for (int j = 0; j < 8; j++)
#pragma unroll
            for (int q = 0; q < 4; q++) acc[i][j][q] = 0.0f;

    // load mapping: 256 threads -> (row slab, 16B segment)
    const int lrow = tid >> 3;   // 0..31
    const int lseg = tid & 7;    // 0..7
    const __half* gA = g_xh + (size_t)(m0 + lrow) * H_DIM + lseg * 8;
    const __half* gB = g_wh + (size_t)(n0 + lrow) * H_DIM + lseg * 8;

#define LOAD_STAGE(c, s) do {                                                  \
    const uint32_t base = sb + (s) * STAGE_BYTES;                              \
    const int koff = (c) * KC;                                                 \
    _Pragma("unroll")                                                          \
    for (int it = 0; it < 4; it++) {                                           \
        int row = it * 32 + lrow;                                              \
        uint32_t off = SW128((uint32_t)(row * 128 + lseg * 16));               \
        CP_ASYNC16(base + off, gA + (size_t)it * 32 * H_DIM + koff);           \
    }                                                                          \
    _Pragma("unroll")                                                          \
    for (int it = 0; it < 4; it++) {                                           \
        int row = it * 32 + lrow;                                              \
        uint32_t off = SW128((uint32_t)(row * 128 + lseg * 16));               \
        CP_ASYNC16(base + TM * 128 + off, gB + (size_t)it * 32 * H_DIM + koff);\
    }                                                                          \
} while (0)

    LOAD_STAGE(0, 0);
    CP_COMMIT();

    // per-thread ldmatrix row/col components (byte offsets before swizzle)
    const int a_row = m_w + (lane & 15);          // + mi*16
    const int a_colb = (lane >> 4) << 4;          // 0 or 16 bytes
    const int b_row = n_w + (lane & 7) + ((lane >> 4) & 1) * 8;   // + bq*16
    const int b_colb = ((lane >> 3) & 1) << 4;    // 0 or 16 bytes

    for (int c = 0; c < NCHUNK; c++) {
        if (c + 1 < NCHUNK) {
            LOAD_STAGE(c + 1, (c + 1) & 1);
            CP_COMMIT();
            CP_WAIT1();
        } else {
            CP_WAIT0();
        }
        __syncthreads();

        const uint32_t baseA = sb + (c & 1) * STAGE_BYTES;
        const uint32_t baseB = baseA + TM * 128;

#pragma unroll
        for (int ks = 0; ks < KC / 16; ks++) {
            uint32_t a[2][4], b[4][4];
#pragma unroll
            for (int mi = 0; mi < 2; mi++) {
                uint32_t off = (uint32_t)((a_row + mi * 16) * 128 + ks * 32 + a_colb);
                ldmx4(a[mi], baseA + SW128(off));
            }
#pragma unroll
            for (int bq = 0; bq < 4; bq++) {
                uint32_t off = (uint32_t)((b_row + bq * 16) * 128 + ks * 32 + b_colb);
                ldmx4(b[bq], baseB + SW128(off));
            }
#pragma unroll
            for (int mi = 0; mi < 2; mi++)
#pragma unroll
                for (int bq = 0; bq < 4; bq++) {
                    mma16816(acc[mi][bq * 2 + 0], a[mi], &b[bq][0]);
                    mma16816(acc[mi][bq * 2 + 1], a[mi], &b[bq][2]);
                }
        }
        __syncthreads();
    }

    // epilogue: direct float2 stores
    const int g = lane >> 2, tig = lane & 3;
#pragma unroll
    for (int mi = 0; mi < 2; mi++) {
        const size_t r0 = (size_t)(m0 + m_w + mi * 16 + g);
#pragma unroll
        for (int ni = 0; ni < 8; ni++) {
            const int col = n0 + n_w + ni * 8 + tig * 2;
            *reinterpret_cast<float2*>(C + r0 * H_DIM + col) =
                make_float2(acc[mi][ni][0], acc[mi][ni][1]);
            *reinterpret_cast<float2*>(C + (r0 + 8) * H_DIM + col) =
                make_float2(acc[mi][ni][2], acc[mi][ni][3]);
        }
    }
#undef LOAD_STAGE
}

// ---------------------------------------------------------------------------
__global__ __launch_bounds__(256) void colsum_part(const float* __restrict__ src, int rows_per)
{
    int h = blockIdx.x * 256 + threadIdx.x;
    const float* p = src + (size_t)blockIdx.y * rows_per * H_DIM + h;
    float s = 0.0f;
    for (int r = 0; r < rows_per; r++) s += p[(size_t)r * H_DIM];
    g_part[blockIdx.y * H_DIM + h] = s;
}

__global__ __launch_bounds__(256) void colsum_reduce(int toX, float invB)
{
    int h = blockIdx.x * 256 + threadIdx.x;
    float s = 0.0f;
#pragma unroll
    for (int i = 0; i < SPLIT; i++) s += g_part[i * H_DIM + h];
    if (toX) g_xmean[h] = s * invB;
    else     g_omean[h] = s * invB;
}

__global__ __launch_bounds__(256) void stdp_vec(
    const float* __restrict__ pre_hist, const float* __restrict__ post_hist,
    const float* __restrict__ d_win, const float* __restrict__ d_dec)
{
    int h = blockIdx.x * 256 + threadIdx.x;
    float win = *d_win, dec = *d_dec;
    float a = 0.0f, b = 0.0f;
    for (int i = 0; i < 99; i++) {
        float dt = (float)(HIST_LEN - i) * win;
        float wv = 0.01f * expf(-dt * dec);
        a += wv * pre_hist[(i + 1) * H_DIM + h];
        if (i >= 1) b += wv * post_hist[(i + 1) * H_DIM + h];
    }
    float w99 = 0.01f * expf(-(1.0f * win) * dec);
    b += w99 * g_omean[h];
    g_a[h] = a;
    g_b[h] = b;
}

__global__ __launch_bounds__(256) void scalars_kernel(
    const float* __restrict__ act, const int* __restrict__ d_ptr,
    const float* __restrict__ d_target, const float* __restrict__ d_hrate,
    float* __restrict__ out_hist, int act_len)
{
    __shared__ float red[256];
    int tid = threadIdx.x;

    float s = 0.0f;
    for (int h = tid; h < H_DIM; h += 256) s += g_omean[h];
    red[tid] = s;
    __syncthreads();
    for (int o = 128; o > 0; o >>= 1) {
        if (tid < o) red[tid] += red[tid + o];
        __syncthreads();
    }
    float m = red[0] / (float)H_DIM;
    __syncthreads();

    float as = 0.0f;
    for (int i = tid; i < act_len; i += 256) as += act[i];
    red[tid] = as;
    __syncthreads();
    for (int o = 128; o > 0; o >>= 1) {
        if (tid < o) red[tid] += red[tid + o];
        __syncthreads();
    }
    int ptr = *d_ptr;
    float hist_mean = (red[0] - act[ptr] + m) / (float)act_len;
    float factor = 1.0f + (*d_hrate) * ((*d_target) - hist_mean);

    if (tid == 0) { g_scal[0] = m; g_scal[1] = factor; }

    for (int i = tid; i < act_len; i += 256)
        out_hist[i] = (i == ptr) ? m : act[i];
}

__global__ __launch_bounds__(256) void weights_kernel(
    const float* __restrict__ W, float* __restrict__ out_w)
{
    size_t idx = (size_t)blockIdx.x * 256 + threadIdx.x;
    int r = (int)(idx >> 10);
    int c = (int)(idx & (H_DIM - 1));
    float factor = g_scal[1];
    float v = W[idx] + g_omean[r] * g_a[c] - g_b[r] * g_xmean[c];
    v = fminf(fmaxf(v, -1.0f), 1.0f);
    v *= factor;
    v = fminf(fmaxf(v, -1.0f), 1.0f);
    out_w[idx] = v;
}

__global__ __launch_bounds__(256) void meta_kernel(
    const float* __restrict__ meta, const float* __restrict__ d_mlr,
    float* __restrict__ out_meta)
{
    int h = blockIdx.x * 256 + threadIdx.x;
    float mlr = *d_mlr;
    float v = meta[h] + mlr * (g_omean[h] - meta[h]);
    v = fminf(fmaxf(v, 0.0f), 2.0f);
    out_meta[h] = v;
}

// ---------------------------------------------------------------------------
extern "C" void kernel_launch(void* const* d_in, const int* in_sizes, int n_in,
                              void* d_out, int out_size)
{
    const float* x      = (const float*)d_in[0];
    const float* W      = (const float*)d_in[1];
    const float* meta   = (const float*)d_in[2];
    const float* pre    = (const float*)d_in[3];
    const float* post   = (const float*)d_in[4];
    const float* act    = (const float*)d_in[5];
    const int*   ptr    = (const int*)d_in[6];
    const float* win    = (const float*)d_in[7];
    const float* dec    = (const float*)d_in[8];
    const float* target = (const float*)d_in[9];
    const float* hrate  = (const float*)d_in[10];
    const float* mlr    = (const float*)d_in[11];

    const int H = H_DIM;
    const int B = in_sizes[0] / H;       // 16384
    const int ACT = in_sizes[5];         // 1000

    float* out      = (float*)d_out;
    float* out_w    = out + (size_t)B * H;
    float* out_meta = out_w + (size_t)H * H;
    float* out_hist = out_meta + H;

    const float invB = 1.0f / (float)B;
    const int rows_per = B / SPLIT;

    static bool attr_done = false;
    if (!attr_done) {
        cudaFuncSetAttribute(gemm_mma, cudaFuncAttributeMaxDynamicSharedMemorySize,
                             GEMM_SMEM);
        attr_done = true;
    }

    // 1) conversions (x conv also produces column partial sums)
    dim3 cxgrid(H / 256, SPLIT);
    convert_x<<<cxgrid, 256>>>(x, rows_per);
    colsum_reduce<<<H / 256, 256>>>(1, invB);
    convert_w<<<dim3(32, 32), dim3(32, 8)>>>(W, meta);

    // 2) tensor-core GEMM (mma.sync)
    dim3 ggrid(H / TN, B / TM);
    gemm_mma<<<ggrid, 256, GEMM_SMEM>>>(out);

    // 3) output column means
    colsum_part<<<cxgrid, 256>>>(out, rows_per);
    colsum_reduce<<<H / 256, 256>>>(0, invB);

    // 4) STDP + scalars + weight/meta updates
    stdp_vec<<<H / 256, 256>>>(pre, post, win, dec);
    scalars_kernel<<<1, 256>>>(act, ptr, target, hrate, out_hist, ACT);
    weights_kernel<<<(H * H) / 256, 256>>>(W, out_w);
    meta_kernel<<<H / 256, 256>>>(meta, mlr, out_meta);
}

// round 4
// speedup vs baseline: 5.4350x; 1.0563x over previous
#include <cuda_runtime.h>
#include <cuda_fp16.h>
#include <cstdint>

// ---------------------------------------------------------------------------
// SynapticPlasticityModule on GB300 — mma.sync fp16 GEMM with fused column-sum
// epilogue. Outputs (d_out, fp32): [output B*H][new_w H*H][new_meta H][hist ACT]
// ---------------------------------------------------------------------------

#define H_DIM 1024
#define B_DIM 16384
#define HIST_LEN 100
#define SPLITX 256                          // x column-sum partials
#define MTILES (B_DIM / 128)                // 128 output row-tiles (= opart rows)

#define TM 128
#define TN 128
#define KC 64
#define NCHUNK (H_DIM / KC)                 // 16
#define STAGE_BYTES (TM * 128 + TN * 128)   // 32768
#define GEMM_SMEM (2 * STAGE_BYTES)         // 65536

// __device__ scratch (allocation-free rule: static module storage)
__device__ __half g_xh[(size_t)B_DIM * H_DIM];   // x fp16          (32 MB)
__device__ __half g_wh[(size_t)H_DIM * H_DIM];   // (W*meta)^T fp16 ( 2 MB)
__device__ float  g_xpart[SPLITX * H_DIM];
__device__ float  g_opart[MTILES * H_DIM];
__device__ float  g_xmean[H_DIM];
__device__ float  g_omean[H_DIM];
__device__ float  g_a[H_DIM];
__device__ float  g_b[H_DIM];
__device__ float  g_scal[2];

__device__ __forceinline__ uint32_t smem_u32(const void* p) {
    uint32_t a;
    asm("{ .reg .u64 t; cvta.to.shared.u64 t, %1; cvt.u32.u64 %0, t; }"
        : "=r"(a) : "l"(p));
    return a;
}
#define SW128(off) ((off) ^ (((off) >> 3) & 0x70))

#define CP_ASYNC16(smem_addr, gptr) \
    asm volatile("cp.async.cg.shared.global [%0], [%1], 16;" \
                 :: "r"(smem_addr), "l"(gptr) : "memory")
#define CP_COMMIT() asm volatile("cp.async.commit_group;" ::: "memory")
#define CP_WAIT1()  asm volatile("cp.async.wait_group 1;" ::: "memory")
#define CP_WAIT0()  asm volatile("cp.async.wait_group 0;" ::: "memory")

__device__ __forceinline__ void ldmx4(uint32_t* r, uint32_t addr) {
    asm volatile("ldmatrix.sync.aligned.m8n8.x4.shared.b16 {%0,%1,%2,%3}, [%4];"
                 : "=r"(r[0]), "=r"(r[1]), "=r"(r[2]), "=r"(r[3]) : "r"(addr));
}
__device__ __forceinline__ void mma16816(float* d, const uint32_t* a,
                                         const uint32_t* b) {
    asm volatile(
        "mma.sync.aligned.m16n8k16.row.col.f32.f16.f16.f32 "
        "{%0,%1,%2,%3}, {%4,%5,%6,%7}, {%8,%9}, {%0,%1,%2,%3};"
        : "+f"(d[0]), "+f"(d[1]), "+f"(d[2]), "+f"(d[3])
        : "r"(a[0]), "r"(a[1]), "r"(a[2]), "r"(a[3]), "r"(b[0]), "r"(b[1]));
}

// ---------------------------------------------------------------------------
// convert_x: fp32 -> fp16 (float4 path), fused column partial sums.
// grid (1, SPLITX), block 256. Each thread: 4 columns x 64 rows.
// ---------------------------------------------------------------------------
__global__ __launch_bounds__(256) void convert_x(const float* __restrict__ x)
{
    const int rows_per = B_DIM / SPLITX;     // 64
    const int c4 = threadIdx.x * 4;          // column base
    const size_t row0 = (size_t)blockIdx.y * rows_per;

    float4 s = make_float4(0.f, 0.f, 0.f, 0.f);
    const float* p = x + row0 * H_DIM + c4;
    __half* q = g_xh + row0 * H_DIM + c4;

    for (int r = 0; r < rows_per; r++) {
        float4 v = *reinterpret_cast<const float4*>(p + (size_t)r * H_DIM);
        s.x += v.x; s.y += v.y; s.z += v.z; s.w += v.w;
        __half2 h01 = __floats2half2_rn(v.x, v.y);
        __half2 h23 = __floats2half2_rn(v.z, v.w);
        *reinterpret_cast<uint2*>(q + (size_t)r * H_DIM) =
            make_uint2(*reinterpret_cast<uint32_t*>(&h01),
                       *reinterpret_cast<uint32_t*>(&h23));
    }
    *reinterpret_cast<float4*>(g_xpart + blockIdx.y * H_DIM + c4) = s;
}

__global__ __launch_bounds__(256) void reduce_x(float invB)
{
    int h = blockIdx.x * 256 + threadIdx.x;
    float s = 0.0f;
    for (int i = 0; i < SPLITX; i++) s += g_xpart[i * H_DIM + h];
    g_xmean[h] = s * invB;
}

// convert_w: (W[k][n]*meta[n]) -> g_wh[n][k] fp16 (transposed). grid(32,32) blk(32,8)
__global__ void convert_w(const float* __restrict__ W, const float* __restrict__ meta)
{
    __shared__ float tile[32][33];
    int n0 = blockIdx.x * 32, k0 = blockIdx.y * 32;
    int tx = threadIdx.x, ty = threadIdx.y;
#pragma unroll
    for (int i = ty; i < 32; i += 8)
        tile[i][tx] = W[(size_t)(k0 + i) * H_DIM + n0 + tx] * meta[n0 + tx];
    __syncthreads();
#pragma unroll
    for (int i = ty; i < 32; i += 8)
        g_wh[(size_t)(n0 + i) * H_DIM + k0 + tx] = __float2half_rn(tile[tx][i]);
}

// ---------------------------------------------------------------------------
// GEMM: C[M,N] = A[M,K] @ B[N,K]^T  (fp16 in, fp32 out) + fused column sums.
// ---------------------------------------------------------------------------
__global__ __launch_bounds__(256) void gemm_mma(float* __restrict__ C)
{
    extern __shared__ char smem[];
    const uint32_t sb = smem_u32(smem);
    const int tid  = threadIdx.x;
    const int wid  = tid >> 5;
    const int lane = tid & 31;
    const int m0 = blockIdx.y * TM;
    const int n0 = blockIdx.x * TN;
    const int m_w = (wid & 3) * 32;
    const int n_w = (wid >> 2) * 64;

    float acc[2][8][4];
#pragma unroll
    for (int i = 0; i < 2; i++)
#pragma unroll
        for (int j = 0; j < 8; j++)
#pragma unroll
            for (int q = 0; q < 4; q++) acc[i][j][q] = 0.0f;

    const int lrow = tid >> 3;
    const int lseg = tid & 7;
    const __half* gA = g_xh + (size_t)(m0 + lrow) * H_DIM + lseg * 8;
    const __half* gB = g_wh + (size_t)(n0 + lrow) * H_DIM + lseg * 8;

#define LOAD_STAGE(c, s) do {                                                  \
    const uint32_t base = sb + (s) * STAGE_BYTES;                              \
    const int koff = (c) * KC;                                                 \
    _Pragma("unroll")                                                          \
    for (int it = 0; it < 4; it++) {                                           \
        int row = it * 32 + lrow;                                              \
        uint32_t off = SW128((uint32_t)(row * 128 + lseg * 16));               \
        CP_ASYNC16(base + off, gA + (size_t)it * 32 * H_DIM + koff);           \
    }                                                                          \
    _Pragma("unroll")                                                          \
    for (int it = 0; it < 4; it++) {                                           \
        int row = it * 32 + lrow;                                              \
        uint32_t off = SW128((uint32_t)(row * 128 + lseg * 16));               \
        CP_ASYNC16(base + TM * 128 + off, gB + (size_t)it * 32 * H_DIM + koff);\
    }                                                                          \
} while (0)

    LOAD_STAGE(0, 0);
    CP_COMMIT();

    const int a_row = m_w + (lane & 15);
    const int a_colb = (lane >> 4) << 4;
    const int b_row = n_w + (lane & 7) + ((lane >> 4) & 1) * 8;
    const int b_colb = ((lane >> 3) & 1) << 4;

    for (int c = 0; c < NCHUNK; c++) {
        if (c + 1 < NCHUNK) {
            LOAD_STAGE(c + 1, (c + 1) & 1);
            CP_COMMIT();
            CP_WAIT1();
        } else {
            CP_WAIT0();
        }
        __syncthreads();

        const uint32_t baseA = sb + (c & 1) * STAGE_BYTES;
        const uint32_t baseB = baseA + TM * 128;

#pragma unroll
        for (int ks = 0; ks < KC / 16; ks++) {
            uint32_t a[2][4], b[4][4];
#pragma unroll
            for (int mi = 0; mi < 2; mi++) {
                uint32_t off = (uint32_t)((a_row + mi * 16) * 128 + ks * 32 + a_colb);
                ldmx4(a[mi], baseA + SW128(off));
            }
#pragma unroll
            for (int bq = 0; bq < 4; bq++) {
                uint32_t off = (uint32_t)((b_row + bq * 16) * 128 + ks * 32 + b_colb);
                ldmx4(b[bq], baseB + SW128(off));
            }
#pragma unroll
            for (int mi = 0; mi < 2; mi++)
#pragma unroll
                for (int bq = 0; bq < 4; bq++) {
                    mma16816(acc[mi][bq * 2 + 0], a[mi], &b[bq][0]);
                    mma16816(acc[mi][bq * 2 + 1], a[mi], &b[bq][2]);
                }
        }
        __syncthreads();
    }

    // ---- epilogue 1: store C tile
    const int g = lane >> 2, tig = lane & 3;
#pragma unroll
    for (int mi = 0; mi < 2; mi++) {
        const size_t r0 = (size_t)(m0 + m_w + mi * 16 + g);
#pragma unroll
        for (int ni = 0; ni < 8; ni++) {
            const int col = n0 + n_w + ni * 8 + tig * 2;
            *reinterpret_cast<float2*>(C + r0 * H_DIM + col) =
                make_float2(acc[mi][ni][0], acc[mi][ni][1]);
            *reinterpret_cast<float2*>(C + (r0 + 8) * H_DIM + col) =
                make_float2(acc[mi][ni][2], acc[mi][ni][3]);
        }
    }

    // ---- epilogue 2: fused column sums of this 128x128 tile -> g_opart[by]
    // red[mgrp][col]: per m-warp-group partial column sums (reuse smem)
    float* red = reinterpret_cast<float*>(smem);   // 4 * 128 floats
#pragma unroll
    for (int ni = 0; ni < 8; ni++) {
        float s0 = acc[0][ni][0] + acc[0][ni][2] + acc[1][ni][0] + acc[1][ni][2];
        float s1 = acc[0][ni][1] + acc[0][ni][3] + acc[1][ni][1] + acc[1][ni][3];
#pragma unroll
        for (int o = 4; o < 32; o <<= 1) {
            s0 += __shfl_xor_sync(0xffffffffu, s0, o);
            s1 += __shfl_xor_sync(0xffffffffu, s1, o);
        }
        if (lane < 4) {
            int col = n_w + ni * 8 + lane * 2;
            red[(wid & 3) * 128 + col]     = s0;
            red[(wid & 3) * 128 + col + 1] = s1;
        }
    }
    __syncthreads();
    if (tid < 128) {
        float s = red[tid] + red[128 + tid] + red[256 + tid] + red[384 + tid];
        g_opart[(size_t)blockIdx.y * H_DIM + n0 + tid] = s;
    }
#undef LOAD_STAGE
}

// ---------------------------------------------------------------------------
// reduce_o + STDP fused: omean[h], then a/b weighted history sums.
// ---------------------------------------------------------------------------
__global__ __launch_bounds__(256) void reduce_o_stdp(
    const float* __restrict__ pre_hist, const float* __restrict__ post_hist,
    const float* __restrict__ d_win, const float* __restrict__ d_dec, float invB)
{
    int h = blockIdx.x * 256 + threadIdx.x;
    float s = 0.0f;
    for (int i = 0; i < MTILES; i++) s += g_opart[i * H_DIM + h];
    float om = s * invB;
    g_omean[h] = om;

    float win = *d_win, dec = *d_dec;
    float a = 0.0f, b = 0.0f;
    for (int i = 0; i < 99; i++) {
        float dt = (float)(HIST_LEN - i) * win;
        float wv = 0.01f * expf(-dt * dec);
        a += wv * pre_hist[(i + 1) * H_DIM + h];
        if (i >= 1) b += wv * post_hist[(i + 1) * H_DIM + h];
    }
    float w99 = 0.01f * expf(-(1.0f * win) * dec);
    b += w99 * om;
    g_a[h] = a;
    g_b[h] = b;
}

__global__ __launch_bounds__(256) void scalars_kernel(
    const float* __restrict__ act, const int* __restrict__ d_ptr,
    const float* __restrict__ d_target, const float* __restrict__ d_hrate,
    float* __restrict__ out_hist, int act_len)
{
    __shared__ float red[256];
    int tid = threadIdx.x;

    float s = 0.0f;
    for (int h = tid; h < H_DIM; h += 256) s += g_omean[h];
    red[tid] = s;
    __syncthreads();
    for (int o = 128; o > 0; o >>= 1) {
        if (tid < o) red[tid] += red[tid + o];
        __syncthreads();
    }
    float m = red[0] / (float)H_DIM;
    __syncthreads();

    float as = 0.0f;
    for (int i = tid; i < act_len; i += 256) as += act[i];
    red[tid] = as;
    __syncthreads();
    for (int o = 128; o > 0; o >>= 1) {
        if (tid < o) red[tid] += red[tid + o];
        __syncthreads();
    }
    int ptr = *d_ptr;
    float hist_mean = (red[0] - act[ptr] + m) / (float)act_len;
    float factor = 1.0f + (*d_hrate) * ((*d_target) - hist_mean);

    if (tid == 0) { g_scal[0] = m; g_scal[1] = factor; }

    for (int i = tid; i < act_len; i += 256)
        out_hist[i] = (i == ptr) ? m : act[i];
}

// weights + meta fused
__global__ __launch_bounds__(256) void weights_meta_kernel(
    const float* __restrict__ W, const float* __restrict__ meta,
    const float* __restrict__ d_mlr,
    float* __restrict__ out_w, float* __restrict__ out_meta)
{
    size_t idx = (size_t)blockIdx.x * 256 + threadIdx.x;
    int r = (int)(idx >> 10);
    int c = (int)(idx & (H_DIM - 1));
    float factor = g_scal[1];
    float v = W[idx] + g_omean[r] * g_a[c] - g_b[r] * g_xmean[c];
    v = fminf(fmaxf(v, -1.0f), 1.0f);
    v *= factor;
    v = fminf(fmaxf(v, -1.0f), 1.0f);
    out_w[idx] = v;

    if (idx < H_DIM) {
        float mlr = *d_mlr;
        float mv = meta[idx] + mlr * (g_omean[idx] - meta[idx]);
        out_meta[idx] = fminf(fmaxf(mv, 0.0f), 2.0f);
    }
}

// ---------------------------------------------------------------------------
extern "C" void kernel_launch(void* const* d_in, const int* in_sizes, int n_in,
                              void* d_out, int out_size)
{
    const float* x      = (const float*)d_in[0];
    const float* W      = (const float*)d_in[1];
    const float* meta   = (const float*)d_in[2];
    const float* pre    = (const float*)d_in[3];
    const float* post   = (const float*)d_in[4];
    const float* act    = (const float*)d_in[5];
    const int*   ptr    = (const int*)d_in[6];
    const float* win    = (const float*)d_in[7];
    const float* dec    = (const float*)d_in[8];
    const float* target = (const float*)d_in[9];
    const float* hrate  = (const float*)d_in[10];
    const float* mlr    = (const float*)d_in[11];

    const int H = H_DIM;
    const int B = in_sizes[0] / H;       // 16384
    const int ACT = in_sizes[5];         // 1000

    float* out      = (float*)d_out;
    float* out_w    = out + (size_t)B * H;
    float* out_meta = out_w + (size_t)H * H;
    float* out_hist = out_meta + H;

    const float invB = 1.0f / (float)B;

    static bool attr_done = false;
    if (!attr_done) {
        cudaFuncSetAttribute(gemm_mma, cudaFuncAttributeMaxDynamicSharedMemorySize,
                             GEMM_SMEM);
        attr_done = true;
    }

    // conversions + x column means
    convert_x<<<dim3(1, SPLITX), 256>>>(x);
    convert_w<<<dim3(32, 32), dim3(32, 8)>>>(W, meta);
    reduce_x<<<H / 256, 256>>>(invB);

    // GEMM (+ fused output column partials)
    dim3 ggrid(H / TN, B / TM);
    gemm_mma<<<ggrid, 256, GEMM_SMEM>>>(out);

    // omean + STDP, scalars, weights+meta
    reduce_o_stdp<<<H / 256, 256>>>(pre, post, win, dec, invB);
    scalars_kernel<<<1, 256>>>(act, ptr, target, hrate, out_hist, ACT);
    weights_meta_kernel<<<(H * H) / 256, 256>>>(W, meta, mlr, out_w, out_meta);
}